// round 7
// baseline (speedup 1.0000x reference)
#include <cuda_runtime.h>
#include <cuda_bf16.h>

// ---------------------------------------------------------------------------
// YOLO loss reduction: 1024 x 28 x 28 cells, B=2 boxes, 20 classes -> 5 scalars
// Fused streaming design: pred is read as float2 (15 per cell); cls channels
// (pos>=5) are consumed INLINE against tcls (never staged), box channels
// (pos<5) go to a compact stride-11 smem buffer (conflict-free: gcd(11,32)=1).
// smem/CTA = 12.4 KB -> high occupancy.  Single launch, last-block finalize,
// self-resetting accumulators (graph-replay deterministic).
// ---------------------------------------------------------------------------

#define NTILES   3136        // 802816 / 256
#define TPB      256
#define INV_S    0.0357142857142857f   // 1/28
#define N_BATCH  1024.0

__device__ double       g_acc[4];   // cls, nbj, reg, cobj raw sums (zero-init)
__device__ unsigned int g_count;    // finished-block ticket (zero-init)

__global__ void __launch_bounds__(TPB, 6) yolo_main_k(
    const float* __restrict__ pred,   // [802816, 30]
    const float* __restrict__ tbox,   // [802816, 4]
    const float* __restrict__ tcls,   // [802816, 20]
    const unsigned int* __restrict__ mask,  // [802816] words, truth <=> w != 0
    float*       __restrict__ out)
{
    __shared__ float bs[TPB * 11];   // box channels, stride 11 (10 used + pad)
    __shared__ float smk[TPB];       // mask as float (for box phase)
    __shared__ float red[8][4];

    const int tid   = threadIdx.x;
    const int cell0 = blockIdx.x * TPB;

    // mask for this thread's own cell (box phase)
    smk[tid] = (mask[cell0 + tid] != 0u) ? 1.0f : 0.0f;

    // tbox: direct coalesced float4
    const float4 tbv = ((const float4*)tbox)[cell0 + tid];

    // ---- fused streaming pass: pred float2 -> (box: STS) | (cls: inline) ---
    // e2 in [0,3840): cell = e2/15, pos = e2%15.  pos<5 -> channels 2pos,2pos+1
    // are box (ch 0..9); pos>=5 -> cls channels (ch 10..28), and the matching
    // tcls float2 at cell*20 + 2*pos-10 is 8-byte aligned.
    float acc_cls = 0.0f;
    {
        const float2* p2  = (const float2*)(pred + (size_t)cell0 * 30);
        const float*  tcg = tcls + (size_t)cell0 * 20;
        const unsigned int* mkg = mask + cell0;
        #pragma unroll
        for (int j = 0; j < 15; j++) {
            int e2  = tid + TPB * j;
            int cl  = e2 / 15;
            int pos = e2 - cl * 15;
            float2 v = p2[e2];
            if (pos < 5) {
                bs[cl * 11 + 2 * pos]     = v.x;
                bs[cl * 11 + 2 * pos + 1] = v.y;
            } else {
                float mm = (mkg[cl] != 0u) ? 1.0f : 0.0f;
                float2 t = *(const float2*)(tcg + cl * 20 + 2 * pos - 10);
                float d0 = v.x - t.x;
                float d1 = v.y - t.y;
                acc_cls += mm * (d0 * d0 + d1 * d1);
            }
        }
    }
    __syncthreads();   // bs + smk visible

    // ---- per-cell box terms (compact smem, conflict-free stride 11) --------
    float acc_nbj, acc_reg, acc_cobj;
    {
        const float* p = bs + tid * 11;
        const float  m = smk[tid];

        float tcx = tbv.x * INV_S, tcy = tbv.y * INV_S;
        float thw = 0.5f * tbv.z, thh = 0.5f * tbv.w;
        float tbx1 = tcx - thw, tby1 = tcy - thh;
        float tbx2 = tcx + thw, tby2 = tcy + thh;
        float ta = (tbx2 - tbx1) * (tby2 - tby1);

        float bx1[2], by1[2], bx2[2], by2[2], iou[2], cf[2];
        #pragma unroll
        for (int b = 0; b < 2; b++) {
            float x = p[5 * b + 0], y = p[5 * b + 1];
            float w = p[5 * b + 2], h = p[5 * b + 3];
            cf[b] = p[5 * b + 4];
            float cx = x * INV_S, cy = y * INV_S;
            float hw = 0.5f * w, hh = 0.5f * h;
            bx1[b] = cx - hw; by1[b] = cy - hh;
            bx2[b] = cx + hw; by2[b] = cy + hh;
            float ltx = fmaxf(bx1[b], tbx1), lty = fmaxf(by1[b], tby1);
            float rbx = fminf(bx2[b], tbx2), rby = fminf(by2[b], tby2);
            float wi = fmaxf(rbx - ltx, 0.0f), hi = fmaxf(rby - lty, 0.0f);
            float inter = wi * hi;
            float a1 = (bx2[b] - bx1[b]) * (by2[b] - by1[b]);
            iou[b] = inter / (a1 + ta - inter);
        }

        int best = (iou[1] > iou[0]) ? 1 : 0;   // first max wins (jnp.argmax)
        float biou = iou[best];
        float bbx1 = bx1[best], bby1 = by1[best];
        float bbx2 = bx2[best], bby2 = by2[best];
        float bconf = cf[best];
        if (!(biou > 0.0f)) {
            bbx1 = bby1 = bbx2 = bby2 = 0.0f;
            bconf = 0.0f; biou = 0.0f;
        }

        float dx = bbx1 - tbx1, dy = bby1 - tby1;
        float lxy = dx * dx + dy * dy;
        float s1 = (bbx2 > 0.0f) ? sqrtf(bbx2) : 0.0f;
        float s2 = (bby2 > 0.0f) ? sqrtf(bby2) : 0.0f;
        float t1 = (tbx2 > 0.0f) ? sqrtf(tbx2) : 0.0f;
        float t2 = (tby2 > 0.0f) ? sqrtf(tby2) : 0.0f;
        float dw = s1 - t1, dh = s2 - t2;
        float lwh = dw * dw + dh * dh;

        acc_reg  = m * (lxy + lwh);
        float dc = bconf - biou;
        acc_cobj = m * dc * dc;
        acc_nbj  = (1.0f - m) * (cf[0] * cf[0] + cf[1] * cf[1]);
    }

    // ---- reduction: warp shuffle -> shared -> double atomics ---------------
    float a4[4] = { acc_cls, acc_nbj, acc_reg, acc_cobj };
    #pragma unroll
    for (int j = 0; j < 4; j++) {
        #pragma unroll
        for (int o = 16; o; o >>= 1)
            a4[j] += __shfl_down_sync(0xffffffffu, a4[j], o);
    }
    int warp = tid >> 5, lane = tid & 31;
    if (lane == 0) {
        red[warp][0] = a4[0]; red[warp][1] = a4[1];
        red[warp][2] = a4[2]; red[warp][3] = a4[3];
    }
    __syncthreads();
    if (tid == 0) {
        double s[4] = {0.0, 0.0, 0.0, 0.0};
        #pragma unroll
        for (int w = 0; w < 8; w++)
            for (int j = 0; j < 4; j++) s[j] += (double)red[w][j];
        atomicAdd(&g_acc[0], s[0]);
        atomicAdd(&g_acc[1], s[1]);
        atomicAdd(&g_acc[2], s[2]);
        atomicAdd(&g_acc[3], s[3]);

        __threadfence();
        unsigned int ticket = atomicAdd(&g_count, 1u);
        if (ticket == NTILES - 1) {
            double cls  = atomicAdd(&g_acc[0], 0.0);
            double nbj  = atomicAdd(&g_acc[1], 0.0);
            double reg  = atomicAdd(&g_acc[2], 0.0);
            double cobj = atomicAdd(&g_acc[3], 0.0);
            double cls_l  = 2.0 * cls / N_BATCH;
            double nbj_l  = 0.5 * nbj / N_BATCH;
            double reg_l  = 5.0 * reg / N_BATCH;
            double cobj_l = cobj / N_BATCH;
            out[0] = (float)(cls_l + nbj_l + reg_l + cobj_l);
            out[1] = (float)reg_l;
            out[2] = (float)cobj_l;
            out[3] = (float)nbj_l;
            out[4] = (float)cls_l;
            // self-reset for the next graph replay
            atomicExch((unsigned long long*)&g_acc[0], 0ull);
            atomicExch((unsigned long long*)&g_acc[1], 0ull);
            atomicExch((unsigned long long*)&g_acc[2], 0ull);
            atomicExch((unsigned long long*)&g_acc[3], 0ull);
            atomicExch(&g_count, 0u);
        }
    }
}

extern "C" void kernel_launch(void* const* d_in, const int* in_sizes, int n_in,
                              void* d_out, int out_size) {
    const float* pred = nullptr;
    const float* tbox = nullptr;
    const float* tcls = nullptr;
    const void*  mask = nullptr;
    for (int i = 0; i < n_in; i++) {
        switch (in_sizes[i]) {
            case 24084480: pred = (const float*)d_in[i]; break;  // 802816*30
            case 16056320: tcls = (const float*)d_in[i]; break;  // 802816*20
            case 3211264:  tbox = (const float*)d_in[i]; break;  // 802816*4
            case 802816:   mask = d_in[i];               break;  // 802816
        }
    }
    yolo_main_k<<<NTILES, TPB>>>(pred, tbox, tcls,
                                 (const unsigned int*)mask, (float*)d_out);
}

// round 9
// speedup vs baseline: 1.0499x; 1.0499x over previous
#include <cuda_runtime.h>
#include <cuda_bf16.h>

// ---------------------------------------------------------------------------
// YOLO loss reduction: 1024 x 28 x 28 cells, B=2 boxes, 20 classes -> 5 scalars
// Round 8: ZERO contended atomics.  Each block writes its 4 partial sums to a
// private slot (plain STG); a tiny second kernel reduces 3136 slots -> out.
// Deterministic across graph replays (slots fully overwritten, fixed-order
// reduction).  Compute structure = R3 (best measured).
// ---------------------------------------------------------------------------

#define NTILES   3136        // 802816 / 256
#define TPB      256
#define INV_S    0.0357142857142857f   // 1/28
#define N_BATCH  1024.0

__device__ __align__(16) float4 g_part[NTILES];   // per-block partials

// ---- kernel 1: main reduction (one 256-cell tile per block) ----------------
__global__ void __launch_bounds__(TPB) yolo_main_k(
    const float* __restrict__ pred,   // [802816, 30]
    const float* __restrict__ tbox,   // [802816, 4]
    const float* __restrict__ tcls,   // [802816, 20]
    const unsigned int* __restrict__ mask)  // [802816] words, truth <=> w != 0
{
    __shared__ __align__(16) float sp[TPB * 30];   // staged pred tile
    __shared__ float smk[TPB];                     // mask as float
    __shared__ float red[8][4];

    const int tid   = threadIdx.x;
    const int cell0 = blockIdx.x * TPB;

    // --- pred staging: coalesced float4 LDG -> STS (1920 float4) ------------
    {
        const float4* p4  = (const float4*)(pred + (size_t)cell0 * 30);
        float4*       sp4 = (float4*)sp;
        #pragma unroll
        for (int i = tid; i < 1920; i += TPB) sp4[i] = p4[i];
    }

    // --- tcls prefetch into registers (in flight with pred staging) ---------
    float4 tc[5];
    {
        const float4* tcg4 = (const float4*)(tcls + (size_t)cell0 * 20);
        #pragma unroll
        for (int j = 0; j < 5; j++) tc[j] = tcg4[tid + TPB * j];
    }

    // --- tbox + mask: direct coalesced loads --------------------------------
    const float4 tbv = ((const float4*)tbox)[cell0 + tid];
    smk[tid] = (mask[cell0 + tid] != 0u) ? 1.0f : 0.0f;

    __syncthreads();   // sp + smk visible

    // --- class loss: registers (tc) vs shared pred --------------------------
    // e4 in [0,1280): cl = e4/5, ch = 4*(e4%5); float4 never crosses a cell.
    float acc_cls = 0.0f;
    #pragma unroll
    for (int j = 0; j < 5; j++) {
        int e4 = tid + TPB * j;
        int cl = e4 / 5;
        int ch = 4 * (e4 - cl * 5);
        const float* pc = sp + cl * 30 + 10 + ch;
        float mm = smk[cl];
        float d0 = pc[0] - tc[j].x;
        float d1 = pc[1] - tc[j].y;
        float d2 = pc[2] - tc[j].z;
        float d3 = pc[3] - tc[j].w;
        acc_cls += mm * (d0 * d0 + d1 * d1 + d2 * d2 + d3 * d3);
    }

    // --- per-cell box terms --------------------------------------------------
    const float* p = sp + tid * 30;
    const float  m = smk[tid];

    float tcx = tbv.x * INV_S, tcy = tbv.y * INV_S;
    float thw = 0.5f * tbv.z, thh = 0.5f * tbv.w;
    float tbx1 = tcx - thw, tby1 = tcy - thh;
    float tbx2 = tcx + thw, tby2 = tcy + thh;
    float ta = (tbx2 - tbx1) * (tby2 - tby1);

    float bx1[2], by1[2], bx2[2], by2[2], iou[2], cf[2];
    #pragma unroll
    for (int b = 0; b < 2; b++) {
        float x = p[5 * b + 0], y = p[5 * b + 1];
        float w = p[5 * b + 2], h = p[5 * b + 3];
        cf[b] = p[5 * b + 4];
        float cx = x * INV_S, cy = y * INV_S;
        float hw = 0.5f * w, hh = 0.5f * h;
        bx1[b] = cx - hw; by1[b] = cy - hh;
        bx2[b] = cx + hw; by2[b] = cy + hh;
        float ltx = fmaxf(bx1[b], tbx1), lty = fmaxf(by1[b], tby1);
        float rbx = fminf(bx2[b], tbx2), rby = fminf(by2[b], tby2);
        float wi = fmaxf(rbx - ltx, 0.0f), hi = fmaxf(rby - lty, 0.0f);
        float inter = wi * hi;
        float a1 = (bx2[b] - bx1[b]) * (by2[b] - by1[b]);
        iou[b] = inter / (a1 + ta - inter);
    }

    int best = (iou[1] > iou[0]) ? 1 : 0;   // first max wins (jnp.argmax)
    float biou = iou[best];
    float bbx1 = bx1[best], bby1 = by1[best];
    float bbx2 = bx2[best], bby2 = by2[best];
    float bconf = cf[best];
    if (!(biou > 0.0f)) {
        bbx1 = bby1 = bbx2 = bby2 = 0.0f;
        bconf = 0.0f; biou = 0.0f;
    }

    float dx = bbx1 - tbx1, dy = bby1 - tby1;
    float lxy = dx * dx + dy * dy;
    float s1 = (bbx2 > 0.0f) ? sqrtf(bbx2) : 0.0f;
    float s2 = (bby2 > 0.0f) ? sqrtf(bby2) : 0.0f;
    float t1 = (tbx2 > 0.0f) ? sqrtf(tbx2) : 0.0f;
    float t2 = (tby2 > 0.0f) ? sqrtf(tby2) : 0.0f;
    float dw = s1 - t1, dh = s2 - t2;
    float lwh = dw * dw + dh * dh;

    float acc_reg  = m * (lxy + lwh);
    float dc       = bconf - biou;
    float acc_cobj = m * dc * dc;
    float acc_nbj  = (1.0f - m) * (cf[0] * cf[0] + cf[1] * cf[1]);

    // --- block reduction: warp shuffle -> shared -> ONE plain store ----------
    float a4[4] = { acc_cls, acc_nbj, acc_reg, acc_cobj };
    #pragma unroll
    for (int j = 0; j < 4; j++) {
        #pragma unroll
        for (int o = 16; o; o >>= 1)
            a4[j] += __shfl_down_sync(0xffffffffu, a4[j], o);
    }
    int warp = tid >> 5, lane = tid & 31;
    if (lane == 0) {
        red[warp][0] = a4[0]; red[warp][1] = a4[1];
        red[warp][2] = a4[2]; red[warp][3] = a4[3];
    }
    __syncthreads();
    if (tid == 0) {
        float s0 = 0.f, s1s = 0.f, s2s = 0.f, s3 = 0.f;
        #pragma unroll
        for (int w = 0; w < 8; w++) {
            s0 += red[w][0]; s1s += red[w][1];
            s2s += red[w][2]; s3 += red[w][3];
        }
        g_part[blockIdx.x] = make_float4(s0, s1s, s2s, s3);  // private slot
    }
}

// ---- kernel 2: reduce 3136 partials -> 5 outputs ---------------------------
__global__ void __launch_bounds__(TPB) yolo_reduce_k(float* __restrict__ out) {
    __shared__ double rd[8][4];
    const int tid = threadIdx.x;

    double s0 = 0.0, s1 = 0.0, s2 = 0.0, s3 = 0.0;
    for (int i = tid; i < NTILES; i += TPB) {
        float4 v = g_part[i];
        s0 += (double)v.x; s1 += (double)v.y;
        s2 += (double)v.z; s3 += (double)v.w;
    }
    #pragma unroll
    for (int o = 16; o; o >>= 1) {
        s0 += __shfl_down_sync(0xffffffffu, s0, o);
        s1 += __shfl_down_sync(0xffffffffu, s1, o);
        s2 += __shfl_down_sync(0xffffffffu, s2, o);
        s3 += __shfl_down_sync(0xffffffffu, s3, o);
    }
    int warp = tid >> 5, lane = tid & 31;
    if (lane == 0) { rd[warp][0] = s0; rd[warp][1] = s1; rd[warp][2] = s2; rd[warp][3] = s3; }
    __syncthreads();
    if (tid == 0) {
        double cls = 0.0, nbj = 0.0, reg = 0.0, cobj = 0.0;
        #pragma unroll
        for (int w = 0; w < 8; w++) {
            cls += rd[w][0]; nbj += rd[w][1]; reg += rd[w][2]; cobj += rd[w][3];
        }
        double cls_l  = 2.0 * cls / N_BATCH;
        double nbj_l  = 0.5 * nbj / N_BATCH;
        double reg_l  = 5.0 * reg / N_BATCH;
        double cobj_l = cobj / N_BATCH;
        out[0] = (float)(cls_l + nbj_l + reg_l + cobj_l);
        out[1] = (float)reg_l;
        out[2] = (float)cobj_l;
        out[3] = (float)nbj_l;
        out[4] = (float)cls_l;
    }
}

extern "C" void kernel_launch(void* const* d_in, const int* in_sizes, int n_in,
                              void* d_out, int out_size) {
    const float* pred = nullptr;
    const float* tbox = nullptr;
    const float* tcls = nullptr;
    const void*  mask = nullptr;
    for (int i = 0; i < n_in; i++) {
        switch (in_sizes[i]) {
            case 24084480: pred = (const float*)d_in[i]; break;  // 802816*30
            case 16056320: tcls = (const float*)d_in[i]; break;  // 802816*20
            case 3211264:  tbox = (const float*)d_in[i]; break;  // 802816*4
            case 802816:   mask = d_in[i];               break;  // 802816
        }
    }
    yolo_main_k<<<NTILES, TPB>>>(pred, tbox, tcls, (const unsigned int*)mask);
    yolo_reduce_k<<<1, TPB>>>((float*)d_out);
}